// round 14
// baseline (speedup 1.0000x reference)
#include <cuda_runtime.h>
#include <math.h>

#define NN   50000
#define NE   800000
#define NF   64
#define NRBF 10
#define NG   512
#define NH   64
#define NTYPE 95
#define NBIN 256
#define NROW (NBIN + 2)

// ---------------- scratch (device globals) ----------------
__device__ float4 g_x4[NN * 16];       // node features
__device__ float4 g_h4[NN * 16];       // pre-message transform
__device__ float4 g_agg4[NN * 16];     // scatter accumulator
__device__ float4 g_gsum4[NG * 16];    // per-graph sums
__device__ float  g_gcnt[NG];          // per-graph counts
__device__ float  g_hemb[NTYPE * NF];  // emb @ W1[0] + b1[0]
__device__ float4 g_ftab[3 * NROW * 16];  // per-conv filter tables f(dist)

// ---------------- helpers ----------------
__device__ __forceinline__ void red_add_v4(float* p, float4 v) {
    asm volatile("red.global.add.v4.f32 [%0], {%1,%2,%3,%4};"
                 :: "l"(p), "f"(v.x), "f"(v.y), "f"(v.z), "f"(v.w) : "memory");
}
__device__ __forceinline__ void red_add_f(float* p, float v) {
    asm volatile("red.global.add.f32 [%0], %1;" :: "l"(p), "f"(v) : "memory");
}
__device__ __forceinline__ float4 ldcg4(const float4* p) {   // L2-only load (no L1 alloc)
    float4 v;
    asm volatile("ld.global.cg.v4.f32 {%0,%1,%2,%3}, [%4];"
                 : "=f"(v.x), "=f"(v.y), "=f"(v.z), "=f"(v.w) : "l"(p));
    return v;
}
__device__ __forceinline__ unsigned long long pack2(float x, float y) {
    unsigned long long r;
    asm("mov.b64 %0, {%1,%2};" : "=l"(r) : "f"(x), "f"(y));
    return r;
}
__device__ __forceinline__ void fma2(unsigned long long& d, unsigned long long a, unsigned long long b) {
    asm("fma.rn.f32x2 %0, %1, %2, %3;" : "=l"(d) : "l"(a), "l"(b), "l"(d));
}
__device__ __forceinline__ float2 unpack2(unsigned long long v) {
    float2 f;
    asm("mov.b64 {%0,%1}, %2;" : "=f"(f.x), "=f"(f.y) : "l"(v));
    return f;
}
__device__ __forceinline__ float sp(float x) {   // stable softplus
    return fmaxf(x, 0.0f) + log1pf(expf(-fabsf(x)));
}

// ---------------- tiny GEMM: g_hemb = emb @ W1[0] + b1[0]  (95 x 64) ----------------
__global__ void k_emb_w1(const float* __restrict__ emb, const float* __restrict__ W,
                         const float* __restrict__ b) {
    __shared__ float Ws[NF * NF];
    int t = threadIdx.x;
    for (int i = t; i < NF * NF; i += 64) Ws[i] = W[i];
    __syncthreads();
    int row = blockIdx.x;
    float acc = b[t];
    const float* er = emb + row * NF;
#pragma unroll 8
    for (int k = 0; k < NF; k++) acc += er[k] * Ws[k * NF + t];
    g_hemb[row * NF + t] = acc;
}

// ---------------- filter tables: ftab[conv][bin][c] = rbf(d_bin) @ We + be ----------------
__global__ void k_ftable(const float* __restrict__ We, const float* __restrict__ be) {
    int bin  = blockIdx.x;        // 0..NROW-1
    int conv = blockIdx.y;        // 0..2
    int c    = threadIdx.x;       // 0..63
    float d = (float)bin * (6.0f / (float)NBIN);
    const float* Wc = We + conv * NRBF * NF;
    float acc = be[conv * NF + c];
#pragma unroll
    for (int r = 0; r < NRBF; r++) {
        float tt = d - 0.66666667f * (float)r;
        acc += expf(-1.125f * tt * tt) * Wc[r * NF + c];
    }
    ((float*)g_ftab)[(conv * NROW + bin) * NF + c] = acc;
}

// ---------------- conv0 front: x = emb[ids], h = hemb[ids], agg = 0, pool zero ----------------
__global__ void k_embed0(const int* __restrict__ ids, const float4* __restrict__ emb4) {
    int t = blockIdx.x * blockDim.x + threadIdx.x;
    if (t < NG * 16) g_gsum4[t] = make_float4(0.f, 0.f, 0.f, 0.f);
    if (t < NG) g_gcnt[t] = 0.0f;
    if (t >= NN * 16) return;
    int n = t >> 4, c = t & 15;
    int id = ids[n];
    g_x4[t] = emb4[(size_t)id * 16 + c];
    g_h4[t] = ((const float4*)g_hemb)[(size_t)id * 16 + c];
    g_agg4[t] = make_float4(0.f, 0.f, 0.f, 0.f);
}

// ================= GEMM core (64 rows, 128 thr, 4 rows x 8 cols/thread) =================
__device__ __forceinline__ void gemm_core(const float4* xs4, const float4* Ws4,
                                          const float* bs, int rl, int cg,
                                          unsigned long long a[4][4]) {
    {
        int cb = cg * 8;
        unsigned long long b0 = pack2(bs[cb + 0], bs[cb + 1]);
        unsigned long long b1 = pack2(bs[cb + 2], bs[cb + 3]);
        unsigned long long b2 = pack2(bs[cb + 4], bs[cb + 5]);
        unsigned long long b3 = pack2(bs[cb + 6], bs[cb + 7]);
#pragma unroll
        for (int i = 0; i < 4; i++) { a[i][0] = b0; a[i][1] = b1; a[i][2] = b2; a[i][3] = b3; }
    }
#pragma unroll 4
    for (int k4 = 0; k4 < 16; k4++) {
        float4 xv[4];
#pragma unroll
        for (int i = 0; i < 4; i++) xv[i] = xs4[(rl + 16 * i) * 17 + k4];
#pragma unroll
        for (int sub = 0; sub < 4; sub++) {
            int k = k4 * 4 + sub;
            const ulonglong2* wp = (const ulonglong2*)(Ws4 + k * 16 + cg * 2);
            ulonglong2 wA = wp[0];
            ulonglong2 wB = wp[1];
#pragma unroll
            for (int i = 0; i < 4; i++) {
                float xk = (sub == 0) ? xv[i].x : (sub == 1) ? xv[i].y : (sub == 2) ? xv[i].z : xv[i].w;
                unsigned long long s = pack2(xk, xk);
                fma2(a[i][0], s, wA.x);
                fma2(a[i][1], s, wA.y);
                fma2(a[i][2], s, wB.x);
                fma2(a[i][3], s, wB.y);
            }
        }
    }
}

// ---------------- fused GEMM pair: softplus-update then next-conv h, one pass ----------------
__global__ __launch_bounds__(128) void k_gemm_fused(
        const float* __restrict__ W2, const float* __restrict__ b2,
        const float* __restrict__ W1n, const float* __restrict__ b1n) {
    __shared__ float4 Ws4[NF * 16];
    __shared__ float4 xs4[64 * 17];
    __shared__ float  bsA[NF], bsB[NF];

    int t = threadIdx.x;
    const float4* W2v = (const float4*)W2;
#pragma unroll
    for (int i = 0; i < 8; i++) Ws4[t + 128 * i] = W2v[t + 128 * i];
    if (t < NF) { bsA[t] = b2[t]; bsB[t] = b1n[t]; }

    int rowbase = blockIdx.x * 64;
#pragma unroll
    for (int i = 0; i < 8; i++) {
        int idx = t + 128 * i;
        int lr = idx >> 4, c = idx & 15;
        int row = rowbase + lr;
        if (row < NN) xs4[lr * 17 + c] = g_agg4[(size_t)row * 16 + c];
    }
    __syncthreads();

    int cg = t & 7;
    int rl = t >> 3;

    unsigned long long a[4][4];
    gemm_core(xs4, Ws4, bsA, rl, cg, a);

    float4 res[4][2];
#pragma unroll
    for (int i = 0; i < 4; i++) {
        int row = rowbase + rl + 16 * i;
        if (row >= NN) continue;
        float2 p0 = unpack2(a[i][0]), p1 = unpack2(a[i][1]);
        float2 p2 = unpack2(a[i][2]), p3 = unpack2(a[i][3]);
        size_t o = (size_t)row * 16 + cg * 2;
        float4 x0 = g_x4[o], x1 = g_x4[o + 1];
        res[i][0] = make_float4(sp(x0.x + p0.x), sp(x0.y + p0.y), sp(x0.z + p1.x), sp(x0.w + p1.y));
        res[i][1] = make_float4(sp(x1.x + p2.x), sp(x1.y + p2.y), sp(x1.z + p3.x), sp(x1.w + p3.y));
        g_x4[o]     = res[i][0];
        g_x4[o + 1] = res[i][1];
    }
    __syncthreads();

#pragma unroll
    for (int i = 0; i < 4; i++) {
        xs4[(rl + 16 * i) * 17 + cg * 2]     = res[i][0];
        xs4[(rl + 16 * i) * 17 + cg * 2 + 1] = res[i][1];
    }
    const float4* W1v = (const float4*)W1n;
#pragma unroll
    for (int i = 0; i < 8; i++) Ws4[t + 128 * i] = W1v[t + 128 * i];
    __syncthreads();

    gemm_core(xs4, Ws4, bsB, rl, cg, a);

#pragma unroll
    for (int i = 0; i < 4; i++) {
        int row = rowbase + rl + 16 * i;
        if (row >= NN) continue;
        float2 p0 = unpack2(a[i][0]), p1 = unpack2(a[i][1]);
        float2 p2 = unpack2(a[i][2]), p3 = unpack2(a[i][3]);
        size_t o = (size_t)row * 16 + cg * 2;
        g_h4[o]     = make_float4(p0.x, p0.y, p1.x, p1.y);
        g_h4[o + 1] = make_float4(p2.x, p2.y, p3.x, p3.y);
        g_agg4[o]     = make_float4(0.f, 0.f, 0.f, 0.f);
        g_agg4[o + 1] = make_float4(0.f, 0.f, 0.f, 0.f);
    }
}

// ---------------- final GEMM + pool ----------------
__global__ __launch_bounds__(128) void k_gemm_final(
        const float* __restrict__ W, const float* __restrict__ b,
        const int* __restrict__ batch) {
    __shared__ float4 Ws4[NF * 16];
    __shared__ float4 xs4[64 * 17];
    __shared__ float  bs[NF];

    int t = threadIdx.x;
    const float4* W4 = (const float4*)W;
#pragma unroll
    for (int i = 0; i < 8; i++) Ws4[t + 128 * i] = W4[t + 128 * i];
    if (t < NF) bs[t] = b[t];

    int rowbase = blockIdx.x * 64;
#pragma unroll
    for (int i = 0; i < 8; i++) {
        int idx = t + 128 * i;
        int lr = idx >> 4, c = idx & 15;
        int row = rowbase + lr;
        if (row < NN) xs4[lr * 17 + c] = g_agg4[(size_t)row * 16 + c];
    }
    __syncthreads();

    int cg = t & 7;
    int rl = t >> 3;

    unsigned long long a[4][4];
    gemm_core(xs4, Ws4, bs, rl, cg, a);

#pragma unroll
    for (int i = 0; i < 4; i++) {
        int row = rowbase + rl + 16 * i;
        if (row >= NN) continue;
        float2 p0 = unpack2(a[i][0]), p1 = unpack2(a[i][1]);
        float2 p2 = unpack2(a[i][2]), p3 = unpack2(a[i][3]);
        size_t o = (size_t)row * 16 + cg * 2;
        float4 x0 = g_x4[o], x1 = g_x4[o + 1];
        x0 = make_float4(sp(x0.x + p0.x), sp(x0.y + p0.y), sp(x0.z + p1.x), sp(x0.w + p1.y));
        x1 = make_float4(sp(x1.x + p2.x), sp(x1.y + p2.y), sp(x1.z + p3.x), sp(x1.w + p3.y));
        int bg = batch[row];
        red_add_v4((float*)(g_gsum4 + (size_t)bg * 16 + cg * 2), x0);
        red_add_v4((float*)(g_gsum4 + (size_t)bg * 16 + cg * 2 + 1), x1);
        if (cg == 0) red_add_f(&g_gcnt[bg], 1.0f);
    }
}

// ---------------- edge kernel: 2 edges/thread, .cg gathers, L1-resident table ----------------
__global__ void k_edge(const int* __restrict__ src, const int* __restrict__ dst,
                       const float* __restrict__ ea, int conv) {
    int t = threadIdx.x;
    int wid = t >> 5, lane = t & 31;
    int sub = lane >> 3;          // edge-pair within warp (0..3)
    int sl  = lane & 7;           // float4 slots sl and sl+8
    int eA = blockIdx.x * 64 + wid * 8 + sub * 2;   // 8 edges per warp
    if (eA >= NE) return;
    int eB = eA + 1;

    // both edges' indices up front
    int   sA = __ldg(src + eA), sB = __ldg(src + eB);
    int   dA = __ldg(dst + eA), dB = __ldg(dst + eB);
    float distA = __ldg(ea + eA), distB = __ldg(ea + eB);

    // issue all 4 gather chains — L2-only (.cg) so the table stays L1-resident
    const float4* hpA = g_h4 + ((sA << 4) + sl);
    const float4* hpB = g_h4 + ((sB << 4) + sl);
    float4 hA0 = ldcg4(hpA);
    float4 hA1 = ldcg4(hpA + 8);
    float4 hB0 = ldcg4(hpB);
    float4 hB1 = ldcg4(hpB + 8);

    // table rows for both edges (default caching -> L1)
    float bfA = distA * ((float)NBIN / 6.0f);
    float bfB = distB * ((float)NBIN / 6.0f);
    int binA = (int)bfA, binB = (int)bfB;
    float frA = bfA - (float)binA, frB = bfB - (float)binB;
    const float4* rowA = g_ftab + (conv * NROW + binA) * 16 + sl;
    const float4* rowB = g_ftab + (conv * NROW + binB) * 16 + sl;
    float4 fa0A = __ldg(rowA),      fa1A = __ldg(rowA + 8);
    float4 fb0A = __ldg(rowA + 16), fb1A = __ldg(rowA + 24);
    float4 fa0B = __ldg(rowB),      fa1B = __ldg(rowB + 8);
    float4 fb0B = __ldg(rowB + 16), fb1B = __ldg(rowB + 24);

    float4 m;
    float* apA = (float*)(g_agg4 + ((dA << 4) + sl));
    m.x = hA0.x * fmaf(frA, fb0A.x - fa0A.x, fa0A.x);
    m.y = hA0.y * fmaf(frA, fb0A.y - fa0A.y, fa0A.y);
    m.z = hA0.z * fmaf(frA, fb0A.z - fa0A.z, fa0A.z);
    m.w = hA0.w * fmaf(frA, fb0A.w - fa0A.w, fa0A.w);
    red_add_v4(apA, m);
    m.x = hA1.x * fmaf(frA, fb1A.x - fa1A.x, fa1A.x);
    m.y = hA1.y * fmaf(frA, fb1A.y - fa1A.y, fa1A.y);
    m.z = hA1.z * fmaf(frA, fb1A.z - fa1A.z, fa1A.z);
    m.w = hA1.w * fmaf(frA, fb1A.w - fa1A.w, fa1A.w);
    red_add_v4(apA + 32, m);

    float* apB = (float*)(g_agg4 + ((dB << 4) + sl));
    m.x = hB0.x * fmaf(frB, fb0B.x - fa0B.x, fa0B.x);
    m.y = hB0.y * fmaf(frB, fb0B.y - fa0B.y, fa0B.y);
    m.z = hB0.z * fmaf(frB, fb0B.z - fa0B.z, fa0B.z);
    m.w = hB0.w * fmaf(frB, fb0B.w - fa0B.w, fa0B.w);
    red_add_v4(apB, m);
    m.x = hB1.x * fmaf(frB, fb1B.x - fa1B.x, fa1B.x);
    m.y = hB1.y * fmaf(frB, fb1B.y - fa1B.y, fa1B.y);
    m.z = hB1.z * fmaf(frB, fb1B.z - fa1B.z, fa1B.z);
    m.w = hB1.w * fmaf(frB, fb1B.w - fa1B.w, fa1B.w);
    red_add_v4(apB + 32, m);
}

// ---------------- head: one block (128 threads) per graph ----------------
__global__ void k_head(const float* __restrict__ Wsm, const float* __restrict__ bsm,
                       const float* __restrict__ Wbg1, const float* __restrict__ bbg1,
                       const float* __restrict__ Wbg2, const float* __restrict__ bbg2,
                       const float* __restrict__ Weh1, const float* __restrict__ beh1,
                       const float* __restrict__ Weh2, const float* __restrict__ beh2,
                       float* __restrict__ out) {
    __shared__ float cs[NF];
    __shared__ float c2[2 * NH];
    __shared__ float red[128];

    int g = blockIdx.x, t = threadIdx.x;
    const float* gsum = (const float*)g_gsum4;

    if (t < NF) {
        float cnt = fmaxf(g_gcnt[g], 1.0f);
        cs[t] = gsum[(size_t)g * NF + t] / cnt;
    }
    __syncthreads();

    {
        float acc = bsm[t];
#pragma unroll 8
        for (int k = 0; k < NF; k++) acc += cs[k] * Wsm[k * 128 + t];
        c2[t] = fmaxf(acc, 0.0f);
    }
    __syncthreads();

    float partial;
    if (t < NH) {
        float acc = bbg1[t];
#pragma unroll 8
        for (int k = 0; k < 2 * NH; k++) acc += c2[k] * Wbg1[k * NH + t];
        partial = fmaxf(acc, 0.0f) * Wbg2[t];
    } else {
        int j = t - NH;
        float acc = beh1[j];
#pragma unroll 8
        for (int k = 0; k < 2 * NH; k++) acc += c2[k] * Weh1[k * NH + j];
        partial = fmaxf(acc, 0.0f) * Weh2[j];
    }
    red[t] = partial;
    __syncthreads();

    int base = t & 64;
    int l = t & 63;
#pragma unroll
    for (int s = 32; s > 0; s >>= 1) {
        if (l < s) red[base + l] += red[base + l + s];
        __syncthreads();
    }
    if (t == 0)  out[g]      = red[0]  + bbg2[0];
    if (t == 64) out[NG + g] = red[64] + beh2[0];
}

// ---------------- launch ----------------
extern "C" void kernel_launch(void* const* d_in, const int* in_sizes, int n_in,
                              void* d_out, int out_size) {
    const int*   x_ids = (const int*)d_in[0];
    const int*   eidx  = (const int*)d_in[1];
    const float* ea    = (const float*)d_in[2];
    const int*   batch = (const int*)d_in[3];
    const float* emb   = (const float*)d_in[4];
    const float* W1    = (const float*)d_in[5];
    const float* b1    = (const float*)d_in[6];
    const float* We    = (const float*)d_in[7];
    const float* be    = (const float*)d_in[8];
    const float* W2    = (const float*)d_in[9];
    const float* b2    = (const float*)d_in[10];
    const float* Wsm   = (const float*)d_in[11];
    const float* bsm   = (const float*)d_in[12];
    const float* Wbg1  = (const float*)d_in[13];
    const float* bbg1  = (const float*)d_in[14];
    const float* Wbg2  = (const float*)d_in[15];
    const float* bbg2  = (const float*)d_in[16];
    const float* Weh1  = (const float*)d_in[17];
    const float* beh1  = (const float*)d_in[18];
    const float* Weh2  = (const float*)d_in[19];
    const float* beh2  = (const float*)d_in[20];

    const int* src = eidx;
    const int* dst = eidx + NE;
    float* out = (float*)d_out;

    const int GB = (NN + 63) / 64;

    k_emb_w1<<<NTYPE, 64>>>(emb, W1, b1);
    dim3 tg(NROW, 3);
    k_ftable<<<tg, 64>>>(We, be);
    k_embed0<<<(NN * 16 + 255) / 256, 256>>>(x_ids, (const float4*)emb);

    // conv0
    k_edge<<<NE / 64, 256>>>(src, dst, ea, 0);
    k_gemm_fused<<<GB, 128>>>(W2, b2, W1 + 1 * NF * NF, b1 + 1 * NF);
    // conv1
    k_edge<<<NE / 64, 256>>>(src, dst, ea, 1);
    k_gemm_fused<<<GB, 128>>>(W2 + 1 * NF * NF, b2 + 1 * NF, W1 + 2 * NF * NF, b1 + 2 * NF);
    // conv2
    k_edge<<<NE / 64, 256>>>(src, dst, ea, 2);
    k_gemm_final<<<GB, 128>>>(W2 + 2 * NF * NF, b2 + 2 * NF, batch);

    k_head<<<NG, 128>>>(Wsm, bsm, Wbg1, bbg1, Wbg2, bbg2, Weh1, beh1, Weh2, beh2, out);
}

// round 15
// speedup vs baseline: 1.0430x; 1.0430x over previous
#include <cuda_runtime.h>
#include <cuda_bf16.h>
#include <math.h>

#define NN   50000
#define NE   800000
#define NF   64
#define NRBF 10
#define NG   512
#define NH   64
#define NTYPE 95
#define NBIN 256
#define NROW (NBIN + 2)

// ---------------- scratch (device globals) ----------------
__device__ float4 g_x4[NN * 16];       // node features
__device__ float4 g_h4[NN * 16];       // pre-message transform
__device__ float4 g_agg4[NN * 16];     // scatter accumulator
__device__ float4 g_gsum4[NG * 16];    // per-graph sums
__device__ float  g_gcnt[NG];          // per-graph counts
__device__ float  g_hemb[NTYPE * NF];  // emb @ W1[0] + b1[0]
__device__ uint4  g_ftabh[3 * NROW * 8];  // bf16 filter tables, lane-permuted (128B/row)

// ---------------- helpers ----------------
__device__ __forceinline__ void red_add_v4(float* p, float4 v) {
    asm volatile("red.global.add.v4.f32 [%0], {%1,%2,%3,%4};"
                 :: "l"(p), "f"(v.x), "f"(v.y), "f"(v.z), "f"(v.w) : "memory");
}
__device__ __forceinline__ void red_add_f(float* p, float v) {
    asm volatile("red.global.add.f32 [%0], %1;" :: "l"(p), "f"(v) : "memory");
}
__device__ __forceinline__ unsigned long long pack2(float x, float y) {
    unsigned long long r;
    asm("mov.b64 %0, {%1,%2};" : "=l"(r) : "f"(x), "f"(y));
    return r;
}
__device__ __forceinline__ void fma2(unsigned long long& d, unsigned long long a, unsigned long long b) {
    asm("fma.rn.f32x2 %0, %1, %2, %3;" : "=l"(d) : "l"(a), "l"(b), "l"(d));
}
__device__ __forceinline__ float2 unpack2(unsigned long long v) {
    float2 f;
    asm("mov.b64 {%0,%1}, %2;" : "=f"(f.x), "=f"(f.y) : "l"(v));
    return f;
}
__device__ __forceinline__ float2 bf2f(unsigned u) {
    __nv_bfloat162 h = *reinterpret_cast<__nv_bfloat162*>(&u);
    return __bfloat1622float2(h);
}
__device__ __forceinline__ float sp(float x) {   // stable softplus
    return fmaxf(x, 0.0f) + log1pf(expf(-fabsf(x)));
}

// ---------------- front setup: filter tables (bf16, permuted) + hemb GEMM ----------------
// grid (NROW, 4): y<3 -> table row for conv y; y==3 -> hemb = emb@W1[0]+b1[0]
__global__ void k_front(const float* __restrict__ We, const float* __restrict__ be,
                        const float* __restrict__ emb, const float* __restrict__ W1,
                        const float* __restrict__ b1) {
    int t = threadIdx.x;          // 0..63
    if (blockIdx.y == 3) {
        __shared__ float Ws[NF * NF];
        if (blockIdx.x >= NTYPE) return;
        for (int i = t; i < NF * NF; i += 64) Ws[i] = W1[i];
        __syncthreads();
        int row = blockIdx.x;
        float acc = b1[t];
        const float* er = emb + row * NF;
#pragma unroll 8
        for (int k = 0; k < NF; k++) acc += er[k] * Ws[k * NF + t];
        g_hemb[row * NF + t] = acc;
        return;
    }
    int bin  = blockIdx.x;        // 0..NROW-1
    int conv = blockIdx.y;        // 0..2
    int c    = t;                 // feature 0..63
    float d = (float)bin * (6.0f / (float)NBIN);
    const float* Wc = We + conv * NRBF * NF;
    float acc = be[conv * NF + c];
#pragma unroll
    for (int r = 0; r < NRBF; r++) {
        float tt = d - 0.66666667f * (float)r;
        acc += expf(-1.125f * tt * tt) * Wc[r * NF + c];
    }
    // permuted position: lane sl = (c%32)/4 owns feats {4sl..4sl+3, 32+4sl..32+4sl+3}
    int sl  = (c & 31) >> 2;
    int hi  = c >> 5;
    int pos = sl * 8 + hi * 4 + (c & 3);
    ((__nv_bfloat16*)g_ftabh)[((size_t)(conv * NROW + bin)) * 64 + pos] = __float2bfloat16(acc);
}

// ---------------- conv0 front: x = emb[ids], h = hemb[ids], agg = 0, pool zero ----------------
__global__ void k_embed0(const int* __restrict__ ids, const float4* __restrict__ emb4) {
    int t = blockIdx.x * blockDim.x + threadIdx.x;
    if (t < NG * 16) g_gsum4[t] = make_float4(0.f, 0.f, 0.f, 0.f);
    if (t < NG) g_gcnt[t] = 0.0f;
    if (t >= NN * 16) return;
    int n = t >> 4, c = t & 15;
    int id = ids[n];
    g_x4[t] = emb4[(size_t)id * 16 + c];
    g_h4[t] = ((const float4*)g_hemb)[(size_t)id * 16 + c];
    g_agg4[t] = make_float4(0.f, 0.f, 0.f, 0.f);
}

// ================= GEMM core (64 rows, 128 thr, 4 rows x 8 cols/thread) =================
__device__ __forceinline__ void gemm_core(const float4* xs4, const float4* Ws4,
                                          const float* bs, int rl, int cg,
                                          unsigned long long a[4][4]) {
    {
        int cb = cg * 8;
        unsigned long long b0 = pack2(bs[cb + 0], bs[cb + 1]);
        unsigned long long b1 = pack2(bs[cb + 2], bs[cb + 3]);
        unsigned long long b2 = pack2(bs[cb + 4], bs[cb + 5]);
        unsigned long long b3 = pack2(bs[cb + 6], bs[cb + 7]);
#pragma unroll
        for (int i = 0; i < 4; i++) { a[i][0] = b0; a[i][1] = b1; a[i][2] = b2; a[i][3] = b3; }
    }
#pragma unroll 4
    for (int k4 = 0; k4 < 16; k4++) {
        float4 xv[4];
#pragma unroll
        for (int i = 0; i < 4; i++) xv[i] = xs4[(rl + 16 * i) * 17 + k4];
#pragma unroll
        for (int sub = 0; sub < 4; sub++) {
            int k = k4 * 4 + sub;
            const ulonglong2* wp = (const ulonglong2*)(Ws4 + k * 16 + cg * 2);
            ulonglong2 wA = wp[0];
            ulonglong2 wB = wp[1];
#pragma unroll
            for (int i = 0; i < 4; i++) {
                float xk = (sub == 0) ? xv[i].x : (sub == 1) ? xv[i].y : (sub == 2) ? xv[i].z : xv[i].w;
                unsigned long long s = pack2(xk, xk);
                fma2(a[i][0], s, wA.x);
                fma2(a[i][1], s, wA.y);
                fma2(a[i][2], s, wB.x);
                fma2(a[i][3], s, wB.y);
            }
        }
    }
}

// ---------------- fused GEMM pair: softplus-update then next-conv h, one pass ----------------
__global__ __launch_bounds__(128) void k_gemm_fused(
        const float* __restrict__ W2, const float* __restrict__ b2,
        const float* __restrict__ W1n, const float* __restrict__ b1n) {
    __shared__ float4 Ws4[NF * 16];
    __shared__ float4 xs4[64 * 17];
    __shared__ float  bsA[NF], bsB[NF];

    int t = threadIdx.x;
    const float4* W2v = (const float4*)W2;
#pragma unroll
    for (int i = 0; i < 8; i++) Ws4[t + 128 * i] = W2v[t + 128 * i];
    if (t < NF) { bsA[t] = b2[t]; bsB[t] = b1n[t]; }

    int rowbase = blockIdx.x * 64;
#pragma unroll
    for (int i = 0; i < 8; i++) {
        int idx = t + 128 * i;
        int lr = idx >> 4, c = idx & 15;
        int row = rowbase + lr;
        if (row < NN) xs4[lr * 17 + c] = g_agg4[(size_t)row * 16 + c];
    }
    __syncthreads();

    int cg = t & 7;
    int rl = t >> 3;

    unsigned long long a[4][4];
    gemm_core(xs4, Ws4, bsA, rl, cg, a);

    float4 res[4][2];
#pragma unroll
    for (int i = 0; i < 4; i++) {
        int row = rowbase + rl + 16 * i;
        if (row >= NN) continue;
        float2 p0 = unpack2(a[i][0]), p1 = unpack2(a[i][1]);
        float2 p2 = unpack2(a[i][2]), p3 = unpack2(a[i][3]);
        size_t o = (size_t)row * 16 + cg * 2;
        float4 x0 = g_x4[o], x1 = g_x4[o + 1];
        res[i][0] = make_float4(sp(x0.x + p0.x), sp(x0.y + p0.y), sp(x0.z + p1.x), sp(x0.w + p1.y));
        res[i][1] = make_float4(sp(x1.x + p2.x), sp(x1.y + p2.y), sp(x1.z + p3.x), sp(x1.w + p3.y));
        g_x4[o]     = res[i][0];
        g_x4[o + 1] = res[i][1];
    }
    __syncthreads();

#pragma unroll
    for (int i = 0; i < 4; i++) {
        xs4[(rl + 16 * i) * 17 + cg * 2]     = res[i][0];
        xs4[(rl + 16 * i) * 17 + cg * 2 + 1] = res[i][1];
    }
    const float4* W1v = (const float4*)W1n;
#pragma unroll
    for (int i = 0; i < 8; i++) Ws4[t + 128 * i] = W1v[t + 128 * i];
    __syncthreads();

    gemm_core(xs4, Ws4, bsB, rl, cg, a);

#pragma unroll
    for (int i = 0; i < 4; i++) {
        int row = rowbase + rl + 16 * i;
        if (row >= NN) continue;
        float2 p0 = unpack2(a[i][0]), p1 = unpack2(a[i][1]);
        float2 p2 = unpack2(a[i][2]), p3 = unpack2(a[i][3]);
        size_t o = (size_t)row * 16 + cg * 2;
        g_h4[o]     = make_float4(p0.x, p0.y, p1.x, p1.y);
        g_h4[o + 1] = make_float4(p2.x, p2.y, p3.x, p3.y);
        g_agg4[o]     = make_float4(0.f, 0.f, 0.f, 0.f);
        g_agg4[o + 1] = make_float4(0.f, 0.f, 0.f, 0.f);
    }
}

// ---------------- final GEMM + pool ----------------
__global__ __launch_bounds__(128) void k_gemm_final(
        const float* __restrict__ W, const float* __restrict__ b,
        const int* __restrict__ batch) {
    __shared__ float4 Ws4[NF * 16];
    __shared__ float4 xs4[64 * 17];
    __shared__ float  bs[NF];

    int t = threadIdx.x;
    const float4* W4 = (const float4*)W;
#pragma unroll
    for (int i = 0; i < 8; i++) Ws4[t + 128 * i] = W4[t + 128 * i];
    if (t < NF) bs[t] = b[t];

    int rowbase = blockIdx.x * 64;
#pragma unroll
    for (int i = 0; i < 8; i++) {
        int idx = t + 128 * i;
        int lr = idx >> 4, c = idx & 15;
        int row = rowbase + lr;
        if (row < NN) xs4[lr * 17 + c] = g_agg4[(size_t)row * 16 + c];
    }
    __syncthreads();

    int cg = t & 7;
    int rl = t >> 3;

    unsigned long long a[4][4];
    gemm_core(xs4, Ws4, bs, rl, cg, a);

#pragma unroll
    for (int i = 0; i < 4; i++) {
        int row = rowbase + rl + 16 * i;
        if (row >= NN) continue;
        float2 p0 = unpack2(a[i][0]), p1 = unpack2(a[i][1]);
        float2 p2 = unpack2(a[i][2]), p3 = unpack2(a[i][3]);
        size_t o = (size_t)row * 16 + cg * 2;
        float4 x0 = g_x4[o], x1 = g_x4[o + 1];
        x0 = make_float4(sp(x0.x + p0.x), sp(x0.y + p0.y), sp(x0.z + p1.x), sp(x0.w + p1.y));
        x1 = make_float4(sp(x1.x + p2.x), sp(x1.y + p2.y), sp(x1.z + p3.x), sp(x1.w + p3.y));
        int bg = batch[row];
        red_add_v4((float*)(g_gsum4 + (size_t)bg * 16 + cg * 2), x0);
        red_add_v4((float*)(g_gsum4 + (size_t)bg * 16 + cg * 2 + 1), x1);
        if (cg == 0) red_add_f(&g_gcnt[bg], 1.0f);
    }
}

// ---------------- edge kernel: 2 edges/thread, bf16 1-line table rows ----------------
__global__ void k_edge(const int* __restrict__ src, const int* __restrict__ dst,
                       const float* __restrict__ ea, int conv) {
    int t = threadIdx.x;
    int wid = t >> 5, lane = t & 31;
    int sub = lane >> 3;          // edge-pair within warp (0..3)
    int sl  = lane & 7;           // float4 slots sl and sl+8
    int eA = blockIdx.x * 64 + wid * 8 + sub * 2;   // 8 edges per warp
    if (eA >= NE) return;
    int eB = eA + 1;

    int   sA = __ldg(src + eA), sB = __ldg(src + eB);
    int   dA = __ldg(dst + eA), dB = __ldg(dst + eB);
    float distA = __ldg(ea + eA), distB = __ldg(ea + eB);

    // gathers (fp32, 2 chains per edge)
    const float4* hpA = g_h4 + ((sA << 4) + sl);
    const float4* hpB = g_h4 + ((sB << 4) + sl);
    float4 hA0 = __ldg(hpA);
    float4 hA1 = __ldg(hpA + 8);
    float4 hB0 = __ldg(hpB);
    float4 hB1 = __ldg(hpB + 8);

    // bf16 table rows (128B each): one uint4 per lane per bin
    float bfA = distA * ((float)NBIN / 6.0f);
    float bfB = distB * ((float)NBIN / 6.0f);
    int binA = (int)bfA, binB = (int)bfB;
    float frA = bfA - (float)binA, frB = bfB - (float)binB;
    const uint4* tb = g_ftabh;
    uint4 ra0 = __ldg(tb + (conv * NROW + binA) * 8 + sl);       // bin
    uint4 ra1 = __ldg(tb + (conv * NROW + binA + 1) * 8 + sl);   // bin+1
    uint4 rb0 = __ldg(tb + (conv * NROW + binB) * 8 + sl);
    uint4 rb1 = __ldg(tb + (conv * NROW + binB + 1) * 8 + sl);

    float2 p;
    float4 f0, g0, f1, g1, m;

    // edge A
    p = bf2f(ra0.x); f0.x = p.x; f0.y = p.y;
    p = bf2f(ra0.y); f0.z = p.x; f0.w = p.y;
    p = bf2f(ra0.z); g0.x = p.x; g0.y = p.y;
    p = bf2f(ra0.w); g0.z = p.x; g0.w = p.y;
    p = bf2f(ra1.x); f1.x = p.x; f1.y = p.y;
    p = bf2f(ra1.y); f1.z = p.x; f1.w = p.y;
    p = bf2f(ra1.z); g1.x = p.x; g1.y = p.y;
    p = bf2f(ra1.w); g1.z = p.x; g1.w = p.y;
    float* apA = (float*)(g_agg4 + ((dA << 4) + sl));
    m.x = hA0.x * fmaf(frA, f1.x - f0.x, f0.x);
    m.y = hA0.y * fmaf(frA, f1.y - f0.y, f0.y);
    m.z = hA0.z * fmaf(frA, f1.z - f0.z, f0.z);
    m.w = hA0.w * fmaf(frA, f1.w - f0.w, f0.w);
    red_add_v4(apA, m);
    m.x = hA1.x * fmaf(frA, g1.x - g0.x, g0.x);
    m.y = hA1.y * fmaf(frA, g1.y - g0.y, g0.y);
    m.z = hA1.z * fmaf(frA, g1.z - g0.z, g0.z);
    m.w = hA1.w * fmaf(frA, g1.w - g0.w, g0.w);
    red_add_v4(apA + 32, m);

    // edge B
    p = bf2f(rb0.x); f0.x = p.x; f0.y = p.y;
    p = bf2f(rb0.y); f0.z = p.x; f0.w = p.y;
    p = bf2f(rb0.z); g0.x = p.x; g0.y = p.y;
    p = bf2f(rb0.w); g0.z = p.x; g0.w = p.y;
    p = bf2f(rb1.x); f1.x = p.x; f1.y = p.y;
    p = bf2f(rb1.y); f1.z = p.x; f1.w = p.y;
    p = bf2f(rb1.z); g1.x = p.x; g1.y = p.y;
    p = bf2f(rb1.w); g1.z = p.x; g1.w = p.y;
    float* apB = (float*)(g_agg4 + ((dB << 4) + sl));
    m.x = hB0.x * fmaf(frB, f1.x - f0.x, f0.x);
    m.y = hB0.y * fmaf(frB, f1.y - f0.y, f0.y);
    m.z = hB0.z * fmaf(frB, f1.z - f0.z, f0.z);
    m.w = hB0.w * fmaf(frB, f1.w - f0.w, f0.w);
    red_add_v4(apB, m);
    m.x = hB1.x * fmaf(frB, g1.x - g0.x, g0.x);
    m.y = hB1.y * fmaf(frB, g1.y - g0.y, g0.y);
    m.z = hB1.z * fmaf(frB, g1.z - g0.z, g0.z);
    m.w = hB1.w * fmaf(frB, g1.w - g0.w, g0.w);
    red_add_v4(apB + 32, m);
}

// ---------------- head: one block (128 threads) per graph ----------------
__global__ void k_head(const float* __restrict__ Wsm, const float* __restrict__ bsm,
                       const float* __restrict__ Wbg1, const float* __restrict__ bbg1,
                       const float* __restrict__ Wbg2, const float* __restrict__ bbg2,
                       const float* __restrict__ Weh1, const float* __restrict__ beh1,
                       const float* __restrict__ Weh2, const float* __restrict__ beh2,
                       float* __restrict__ out) {
    __shared__ float cs[NF];
    __shared__ float c2[2 * NH];
    __shared__ float red[128];

    int g = blockIdx.x, t = threadIdx.x;
    const float* gsum = (const float*)g_gsum4;

    if (t < NF) {
        float cnt = fmaxf(g_gcnt[g], 1.0f);
        cs[t] = gsum[(size_t)g * NF + t] / cnt;
    }
    __syncthreads();

    {
        float acc = bsm[t];
#pragma unroll 8
        for (int k = 0; k < NF; k++) acc += cs[k] * Wsm[k * 128 + t];
        c2[t] = fmaxf(acc, 0.0f);
    }
    __syncthreads();

    float partial;
    if (t < NH) {
        float acc = bbg1[t];
#pragma unroll 8
        for (int k = 0; k < 2 * NH; k++) acc += c2[k] * Wbg1[k * NH + t];
        partial = fmaxf(acc, 0.0f) * Wbg2[t];
    } else {
        int j = t - NH;
        float acc = beh1[j];
#pragma unroll 8
        for (int k = 0; k < 2 * NH; k++) acc += c2[k] * Weh1[k * NH + j];
        partial = fmaxf(acc, 0.0f) * Weh2[j];
    }
    red[t] = partial;
    __syncthreads();

    int base = t & 64;
    int l = t & 63;
#pragma unroll
    for (int s = 32; s > 0; s >>= 1) {
        if (l < s) red[base + l] += red[base + l + s];
        __syncthreads();
    }
    if (t == 0)  out[g]      = red[0]  + bbg2[0];
    if (t == 64) out[NG + g] = red[64] + beh2[0];
}

// ---------------- launch ----------------
extern "C" void kernel_launch(void* const* d_in, const int* in_sizes, int n_in,
                              void* d_out, int out_size) {
    const int*   x_ids = (const int*)d_in[0];
    const int*   eidx  = (const int*)d_in[1];
    const float* ea    = (const float*)d_in[2];
    const int*   batch = (const int*)d_in[3];
    const float* emb   = (const float*)d_in[4];
    const float* W1    = (const float*)d_in[5];
    const float* b1    = (const float*)d_in[6];
    const float* We    = (const float*)d_in[7];
    const float* be    = (const float*)d_in[8];
    const float* W2    = (const float*)d_in[9];
    const float* b2    = (const float*)d_in[10];
    const float* Wsm   = (const float*)d_in[11];
    const float* bsm   = (const float*)d_in[12];
    const float* Wbg1  = (const float*)d_in[13];
    const float* bbg1  = (const float*)d_in[14];
    const float* Wbg2  = (const float*)d_in[15];
    const float* bbg2  = (const float*)d_in[16];
    const float* Weh1  = (const float*)d_in[17];
    const float* beh1  = (const float*)d_in[18];
    const float* Weh2  = (const float*)d_in[19];
    const float* beh2  = (const float*)d_in[20];

    const int* src = eidx;
    const int* dst = eidx + NE;
    float* out = (float*)d_out;

    const int GB = (NN + 63) / 64;

    dim3 tg(NROW, 4);
    k_front<<<tg, 64>>>(We, be, emb, W1, b1);
    k_embed0<<<(NN * 16 + 255) / 256, 256>>>(x_ids, (const float4*)emb);

    // conv0
    k_edge<<<NE / 64, 256>>>(src, dst, ea, 0);
    k_gemm_fused<<<GB, 128>>>(W2, b2, W1 + 1 * NF * NF, b1 + 1 * NF);
    // conv1
    k_edge<<<NE / 64, 256>>>(src, dst, ea, 1);
    k_gemm_fused<<<GB, 128>>>(W2 + 1 * NF * NF, b2 + 1 * NF, W1 + 2 * NF * NF, b1 + 2 * NF);
    // conv2
    k_edge<<<NE / 64, 256>>>(src, dst, ea, 2);
    k_gemm_final<<<GB, 128>>>(W2 + 2 * NF * NF, b2 + 2 * NF, batch);

    k_head<<<NG, 128>>>(Wsm, bsm, Wbg1, bbg1, Wbg2, bbg2, Weh1, beh1, Weh2, beh2, out);
}